// round 4
// baseline (speedup 1.0000x reference)
#include <cuda_runtime.h>

#define N_NODES 50000
#define N_EDGES 800000
#define IN_DIM 64
#define EDGE_DIM 32
#define OUT_DIM 64
#define CAP 96                      // bucket capacity; Poisson(16) => P(deg>96) ~ 0
#define NPB 32                      // nodes per block
#define A_STRIDE 161                // 160 + 1 pad float -> conflict-free column reads

// ---- scratch (static device globals: allocation-free) ----
__device__ int  g_deg[N_NODES];
__device__ int2 g_adj[(size_t)N_NODES * CAP];   // (src, edge_id), bucketed per dst
__device__ int  g_is64;                         // edge_index dtype flag

// Fused: zero degrees + detect edge_index dtype.
// int64 edge_index (values < 2^31) => every odd 32-bit word is 0.
__global__ void k_init(const int* __restrict__ ei32) {
    int i = blockIdx.x * blockDim.x + threadIdx.x;
    if (i < N_NODES) g_deg[i] = 0;
    if (blockIdx.x == 0) {
        __shared__ int nz;
        if (threadIdx.x == 0) nz = 0;
        __syncthreads();
        if (ei32[2 * threadIdx.x + 1] != 0) atomicAdd(&nz, 1);
        __syncthreads();
        if (threadIdx.x == 0) g_is64 = (nz == 0) ? 1 : 0;
    }
}

// Single-pass bucket scatter (replaces count + alloc + scatter).
__global__ void k_scatter(const void* __restrict__ ei) {
    int e = blockIdx.x * blockDim.x + threadIdx.x;
    if (e < N_EDGES) {
        int src, dst;
        if (g_is64) {
            src = (int)((const long long*)ei)[e];
            dst = (int)((const long long*)ei)[N_EDGES + e];
        } else {
            src = ((const int*)ei)[e];
            dst = ((const int*)ei)[N_EDGES + e];
        }
        src = min(max(src, 0), N_NODES - 1);
        dst = min(max(dst, 0), N_NODES - 1);
        int pos = atomicAdd(&g_deg[dst], 1);
        if (pos < CAP) g_adj[(size_t)dst * CAP + pos] = make_int2(src, e);
    }
}

// Phase 1: warp-per-4-nodes register reduction of S1 = sum x[src], S2 = sum ea,
// staged as A = [x | S1/deg | S2/deg] (160 floats/node) into smem.
// Phase 2: block GEMM  out[32,64] = A[32,160] @ [self_w; W1; W2] + biases,
// 2x4 register tiling, weights streamed from gmem (L1/L2-resident).
__global__ void __launch_bounds__(256) k_aggregate(
    const float* __restrict__ x,
    const float* __restrict__ ea,
    const float* __restrict__ msg_w,     // [96,64]: rows 0:64 = W1, 64:96 = W2
    const float* __restrict__ msg_b,
    const float* __restrict__ self_w,    // [64,64]
    const float* __restrict__ self_b,
    float* __restrict__ out)
{
    __shared__ float s_a[NPB * A_STRIDE];    // 20.6 KB
    __shared__ float s_deg[NPB];

    const int tid  = threadIdx.x;
    const int lane = tid & 31;
    const int warp = tid >> 5;
    const int blk_node0 = blockIdx.x * NPB;

    // ---- Phase 1: reduction ----
    #pragma unroll
    for (int t = 0; t < 4; ++t) {
        const int row  = warp * 4 + t;
        const int node = blk_node0 + row;
        if (node < N_NODES) {
            const int true_deg = g_deg[node];
            const int d = min(true_deg, CAP);
            const size_t abase = (size_t)node * CAP;
            float a = 0.f, b = 0.f, c = 0.f;
            #pragma unroll 4
            for (int j = 0; j < d; ++j) {
                int2 aep = g_adj[abase + j];
                float2 xv = *reinterpret_cast<const float2*>(x + (size_t)aep.x * IN_DIM + 2 * lane);
                a += xv.x;
                b += xv.y;
                c += ea[(size_t)aep.y * EDGE_DIM + lane];
            }
            const float inv = 1.f / fmaxf((float)true_deg, 1.f);
            float2 xv = *reinterpret_cast<const float2*>(x + (size_t)node * IN_DIM + 2 * lane);
            float* ar = s_a + row * A_STRIDE;
            ar[2 * lane]          = xv.x;
            ar[2 * lane + 1]      = xv.y;
            ar[64 + 2 * lane]     = a * inv;
            ar[64 + 2 * lane + 1] = b * inv;
            ar[128 + lane]        = c * inv;
            if (lane == 0) s_deg[row] = (float)true_deg;
        }
    }
    __syncthreads();

    // ---- Phase 2: block GEMM, thread tile 2 rows x 4 cols ----
    const int tx = tid & 15;        // 16 col-groups
    const int ty = tid >> 4;        // 16 row-pairs
    const int r0 = ty * 2;
    const int c0 = tx * 4;

    const float4 sb = *reinterpret_cast<const float4*>(self_b + c0);
    const float4 mb = *reinterpret_cast<const float4*>(msg_b + c0);
    const float mask0 = (s_deg[r0]     > 0.f) ? 1.f : 0.f;
    const float mask1 = (s_deg[r0 + 1] > 0.f) ? 1.f : 0.f;

    float acc0[4] = { sb.x + mask0 * mb.x, sb.y + mask0 * mb.y,
                      sb.z + mask0 * mb.z, sb.w + mask0 * mb.w };
    float acc1[4] = { sb.x + mask1 * mb.x, sb.y + mask1 * mb.y,
                      sb.z + mask1 * mb.z, sb.w + mask1 * mb.w };

    const float* a0p = s_a + r0 * A_STRIDE;
    const float* a1p = a0p + A_STRIDE;

    #pragma unroll 4
    for (int k = 0; k < IN_DIM; ++k) {          // self part, K = 0..63
        const float a0 = a0p[k];
        const float a1 = a1p[k];
        const float4 w = *reinterpret_cast<const float4*>(self_w + k * OUT_DIM + c0);
        acc0[0] += a0 * w.x; acc0[1] += a0 * w.y; acc0[2] += a0 * w.z; acc0[3] += a0 * w.w;
        acc1[0] += a1 * w.x; acc1[1] += a1 * w.y; acc1[2] += a1 * w.z; acc1[3] += a1 * w.w;
    }
    #pragma unroll 4
    for (int k = 0; k < IN_DIM + EDGE_DIM; ++k) { // message part, K = 64..159
        const float a0 = a0p[64 + k];
        const float a1 = a1p[64 + k];
        const float4 w = *reinterpret_cast<const float4*>(msg_w + k * OUT_DIM + c0);
        acc0[0] += a0 * w.x; acc0[1] += a0 * w.y; acc0[2] += a0 * w.z; acc0[3] += a0 * w.w;
        acc1[0] += a1 * w.x; acc1[1] += a1 * w.y; acc1[2] += a1 * w.z; acc1[3] += a1 * w.w;
    }

    const int n0 = blk_node0 + r0;
    if (n0 < N_NODES)
        *reinterpret_cast<float4*>(out + (size_t)n0 * OUT_DIM + c0) =
            make_float4(acc0[0], acc0[1], acc0[2], acc0[3]);
    if (n0 + 1 < N_NODES)
        *reinterpret_cast<float4*>(out + (size_t)(n0 + 1) * OUT_DIM + c0) =
            make_float4(acc1[0], acc1[1], acc1[2], acc1[3]);
}

extern "C" void kernel_launch(void* const* d_in, const int* in_sizes, int n_in,
                              void* d_out, int out_size) {
    // Identify inputs by element count (robust to metadata ordering):
    //   x=3,200,000  edge_index=1,600,000  edge_attr=25,600,000
    //   msg_w=6,144  self_w=4,096  msg_b/self_b=64 (msg_b first)
    const float* x = 0; const void* ei = 0; const float* ea = 0;
    const float* msg_w = 0; const float* self_w = 0;
    const float* msg_b = 0; const float* self_b = 0;
    for (int i = 0; i < n_in; ++i) {
        const int sz = in_sizes[i];
        if      (sz == N_NODES * IN_DIM)              x      = (const float*)d_in[i];
        else if (sz == 2 * N_EDGES)                   ei     = d_in[i];
        else if (sz == N_EDGES * EDGE_DIM)            ea     = (const float*)d_in[i];
        else if (sz == (IN_DIM + EDGE_DIM) * OUT_DIM) msg_w  = (const float*)d_in[i];
        else if (sz == IN_DIM * OUT_DIM)              self_w = (const float*)d_in[i];
        else if (sz == OUT_DIM) {
            if (!msg_b) msg_b = (const float*)d_in[i];
            else        self_b = (const float*)d_in[i];
        }
    }
    float* out = (float*)d_out;

    k_init<<<(N_NODES + 255) / 256, 256>>>((const int*)ei);
    k_scatter<<<(N_EDGES + 255) / 256, 256>>>(ei);
    k_aggregate<<<(N_NODES + NPB - 1) / NPB, 256>>>(x, ea, msg_w, msg_b, self_w, self_b, out);
}

// round 5
// speedup vs baseline: 1.0142x; 1.0142x over previous
#include <cuda_runtime.h>

#define N_NODES 50000
#define N_EDGES 800000
#define IN_DIM 64
#define EDGE_DIM 32
#define OUT_DIM 64
#define NPB 32                      // nodes per block
#define A_STRIDE 164                // 160 + 4 pad -> 16B-aligned rows, float4 LDS

// ---- scratch (static device globals: allocation-free) ----
__device__ int  g_deg[N_NODES];
__device__ int  g_start[N_NODES];
__device__ int  g_cursor[N_NODES];
__device__ int  g_total;
__device__ int2 g_adj[N_EDGES];          // (src, edge_id) packed per dst segment
__device__ int  g_is64;

// Fused: zero degrees + detect edge_index dtype (int64 => odd 32-bit words all 0).
__global__ void k_init(const int* __restrict__ ei32) {
    int i = blockIdx.x * blockDim.x + threadIdx.x;
    if (i < N_NODES) g_deg[i] = 0;
    if (i == 0) g_total = 0;
    if (blockIdx.x == 0) {
        __shared__ int nz;
        if (threadIdx.x == 0) nz = 0;
        __syncthreads();
        if (ei32[2 * threadIdx.x + 1] != 0) atomicAdd(&nz, 1);
        __syncthreads();
        if (threadIdx.x == 0) g_is64 = (nz == 0) ? 1 : 0;
    }
}

__device__ __forceinline__ int load_idx(const void* ei, int pos) {
    int v;
    if (g_is64) v = (int)((const long long*)ei)[pos];
    else        v = ((const int*)ei)[pos];
    return min(max(v, 0), N_NODES - 1);
}

__global__ void k_count(const void* __restrict__ ei) {
    int e = blockIdx.x * blockDim.x + threadIdx.x;
    if (e < N_EDGES) atomicAdd(&g_deg[load_idx(ei, N_EDGES + e)], 1);
}

// Unordered segment allocator: warp shuffle-scan + one atomicAdd per warp.
__global__ void k_alloc() {
    const int i    = blockIdx.x * blockDim.x + threadIdx.x;
    const int lane = threadIdx.x & 31;
    int d = (i < N_NODES) ? g_deg[i] : 0;
    int s = d;
    #pragma unroll
    for (int off = 1; off < 32; off <<= 1) {
        int v = __shfl_up_sync(0xffffffffu, s, off);
        if (lane >= off) s += v;
    }
    const int excl  = s - d;
    const int total = __shfl_sync(0xffffffffu, s, 31);
    int base = 0;
    if (lane == 31) base = atomicAdd(&g_total, total);
    base = __shfl_sync(0xffffffffu, base, 31);
    if (i < N_NODES) {
        g_start[i]  = base + excl;
        g_cursor[i] = base + excl;
    }
}

__global__ void k_scatter(const void* __restrict__ ei) {
    int e = blockIdx.x * blockDim.x + threadIdx.x;
    if (e < N_EDGES) {
        int src = load_idx(ei, e);
        int dst = load_idx(ei, N_EDGES + e);
        int pos = atomicAdd(&g_cursor[dst], 1);
        pos = min(max(pos, 0), N_EDGES - 1);
        g_adj[pos] = make_int2(src, e);
    }
}

// Phase 1: warp reduces 4 nodes. Adjacency preloaded in ONE coalesced int2 load
// per segment (deg<=32 fast path) and shuffle-extracted -> all x/ea gathers
// independent (high MLP). Results staged as A=[x | S1/deg | S2/deg] in smem.
// Phase 2: block GEMM out[32,64] = A[32,160] @ W[160,64] + biases.
// A via broadcast float4 LDS, W via LDG.128 (L1-resident), 2x4 thread tile.
__global__ void __launch_bounds__(256) k_aggregate(
    const float* __restrict__ x,
    const float* __restrict__ ea,
    const float* __restrict__ msg_w,     // [96,64]: rows 0:64 = W1, 64:96 = W2
    const float* __restrict__ msg_b,
    const float* __restrict__ self_w,    // [64,64]
    const float* __restrict__ self_b,
    float* __restrict__ out)
{
    __shared__ float s_a[NPB * A_STRIDE];    // 21.0 KB
    __shared__ float s_deg[NPB];

    const int tid  = threadIdx.x;
    const int lane = tid & 31;
    const int warp = tid >> 5;
    const int blk_node0 = blockIdx.x * NPB;

    // ---- Phase 1: gather + reduce ----
    #pragma unroll
    for (int t = 0; t < 4; ++t) {
        const int row  = warp * 4 + t;
        const int node = blk_node0 + row;
        if (node < N_NODES) {
            const int beg = g_start[node];
            const int d   = g_deg[node];
            // coalesced segment preload (fast path covers deg<=32)
            int2 my = g_adj[min(beg + lane, N_EDGES - 1)];
            float a = 0.f, b = 0.f, c = 0.f;
            const int dm = min(d, 32);
            #pragma unroll 8
            for (int j = 0; j < dm; ++j) {
                const int s  = __shfl_sync(0xffffffffu, my.x, j);
                const int e2 = __shfl_sync(0xffffffffu, my.y, j);
                float2 xv = *reinterpret_cast<const float2*>(x + (size_t)s * IN_DIM + 2 * lane);
                a += xv.x;
                b += xv.y;
                c += ea[(size_t)e2 * EDGE_DIM + lane];
            }
            for (int j = 32; j < d; ++j) {   // rare tail (P ~ 1e-4 per node)
                int2 aep = g_adj[beg + j];
                float2 xv = *reinterpret_cast<const float2*>(x + (size_t)aep.x * IN_DIM + 2 * lane);
                a += xv.x;
                b += xv.y;
                c += ea[(size_t)aep.y * EDGE_DIM + lane];
            }
            const float inv = 1.f / fmaxf((float)d, 1.f);
            float2 xv = *reinterpret_cast<const float2*>(x + (size_t)node * IN_DIM + 2 * lane);
            float* ar = s_a + row * A_STRIDE;
            ar[2 * lane]          = xv.x;
            ar[2 * lane + 1]      = xv.y;
            ar[64 + 2 * lane]     = a * inv;
            ar[64 + 2 * lane + 1] = b * inv;
            ar[128 + lane]        = c * inv;
            if (lane == 0) s_deg[row] = (float)d;
        }
    }
    __syncthreads();

    // ---- Phase 2: block GEMM, thread tile 2 rows x 4 cols ----
    const int tx = tid & 15;
    const int ty = tid >> 4;
    const int r0 = ty * 2;
    const int c0 = tx * 4;

    const float4 sb = *reinterpret_cast<const float4*>(self_b + c0);
    const float4 mb = *reinterpret_cast<const float4*>(msg_b + c0);
    const float mask0 = (s_deg[r0]     > 0.f) ? 1.f : 0.f;
    const float mask1 = (s_deg[r0 + 1] > 0.f) ? 1.f : 0.f;

    float acc0[4] = { sb.x + mask0 * mb.x, sb.y + mask0 * mb.y,
                      sb.z + mask0 * mb.z, sb.w + mask0 * mb.w };
    float acc1[4] = { sb.x + mask1 * mb.x, sb.y + mask1 * mb.y,
                      sb.z + mask1 * mb.z, sb.w + mask1 * mb.w };

    const float* a0p = s_a + r0 * A_STRIDE;
    const float* a1p = a0p + A_STRIDE;

    #pragma unroll 4
    for (int k = 0; k < IN_DIM; k += 4) {           // self part
        const float4 a0 = *reinterpret_cast<const float4*>(a0p + k);
        const float4 a1 = *reinterpret_cast<const float4*>(a1p + k);
        const float4 w0 = *reinterpret_cast<const float4*>(self_w + (k + 0) * OUT_DIM + c0);
        const float4 w1 = *reinterpret_cast<const float4*>(self_w + (k + 1) * OUT_DIM + c0);
        const float4 w2 = *reinterpret_cast<const float4*>(self_w + (k + 2) * OUT_DIM + c0);
        const float4 w3 = *reinterpret_cast<const float4*>(self_w + (k + 3) * OUT_DIM + c0);
        acc0[0] += a0.x*w0.x + a0.y*w1.x + a0.z*w2.x + a0.w*w3.x;
        acc0[1] += a0.x*w0.y + a0.y*w1.y + a0.z*w2.y + a0.w*w3.y;
        acc0[2] += a0.x*w0.z + a0.y*w1.z + a0.z*w2.z + a0.w*w3.z;
        acc0[3] += a0.x*w0.w + a0.y*w1.w + a0.z*w2.w + a0.w*w3.w;
        acc1[0] += a1.x*w0.x + a1.y*w1.x + a1.z*w2.x + a1.w*w3.x;
        acc1[1] += a1.x*w0.y + a1.y*w1.y + a1.z*w2.y + a1.w*w3.y;
        acc1[2] += a1.x*w0.z + a1.y*w1.z + a1.z*w2.z + a1.w*w3.z;
        acc1[3] += a1.x*w0.w + a1.y*w1.w + a1.z*w2.w + a1.w*w3.w;
    }
    #pragma unroll 4
    for (int k = 0; k < IN_DIM + EDGE_DIM; k += 4) { // message part
        const float4 a0 = *reinterpret_cast<const float4*>(a0p + 64 + k);
        const float4 a1 = *reinterpret_cast<const float4*>(a1p + 64 + k);
        const float4 w0 = *reinterpret_cast<const float4*>(msg_w + (k + 0) * OUT_DIM + c0);
        const float4 w1 = *reinterpret_cast<const float4*>(msg_w + (k + 1) * OUT_DIM + c0);
        const float4 w2 = *reinterpret_cast<const float4*>(msg_w + (k + 2) * OUT_DIM + c0);
        const float4 w3 = *reinterpret_cast<const float4*>(msg_w + (k + 3) * OUT_DIM + c0);
        acc0[0] += a0.x*w0.x + a0.y*w1.x + a0.z*w2.x + a0.w*w3.x;
        acc0[1] += a0.x*w0.y + a0.y*w1.y + a0.z*w2.y + a0.w*w3.y;
        acc0[2] += a0.x*w0.z + a0.y*w1.z + a0.z*w2.z + a0.w*w3.z;
        acc0[3] += a0.x*w0.w + a0.y*w1.w + a0.z*w2.w + a0.w*w3.w;
        acc1[0] += a1.x*w0.x + a1.y*w1.x + a1.z*w2.x + a1.w*w3.x;
        acc1[1] += a1.x*w0.y + a1.y*w1.y + a1.z*w2.y + a1.w*w3.y;
        acc1[2] += a1.x*w0.z + a1.y*w1.z + a1.z*w2.z + a1.w*w3.z;
        acc1[3] += a1.x*w0.w + a1.y*w1.w + a1.z*w2.w + a1.w*w3.w;
    }

    const int n0 = blk_node0 + r0;
    if (n0 < N_NODES)
        *reinterpret_cast<float4*>(out + (size_t)n0 * OUT_DIM + c0) =
            make_float4(acc0[0], acc0[1], acc0[2], acc0[3]);
    if (n0 + 1 < N_NODES)
        *reinterpret_cast<float4*>(out + (size_t)(n0 + 1) * OUT_DIM + c0) =
            make_float4(acc1[0], acc1[1], acc1[2], acc1[3]);
}

extern "C" void kernel_launch(void* const* d_in, const int* in_sizes, int n_in,
                              void* d_out, int out_size) {
    // Identify inputs by element count (robust to metadata ordering):
    const float* x = 0; const void* ei = 0; const float* ea = 0;
    const float* msg_w = 0; const float* self_w = 0;
    const float* msg_b = 0; const float* self_b = 0;
    for (int i = 0; i < n_in; ++i) {
        const int sz = in_sizes[i];
        if      (sz == N_NODES * IN_DIM)              x      = (const float*)d_in[i];
        else if (sz == 2 * N_EDGES)                   ei     = d_in[i];
        else if (sz == N_EDGES * EDGE_DIM)            ea     = (const float*)d_in[i];
        else if (sz == (IN_DIM + EDGE_DIM) * OUT_DIM) msg_w  = (const float*)d_in[i];
        else if (sz == IN_DIM * OUT_DIM)              self_w = (const float*)d_in[i];
        else if (sz == OUT_DIM) {
            if (!msg_b) msg_b = (const float*)d_in[i];
            else        self_b = (const float*)d_in[i];
        }
    }
    float* out = (float*)d_out;

    k_init<<<(N_NODES + 255) / 256, 256>>>((const int*)ei);
    k_count<<<(N_EDGES + 255) / 256, 256>>>(ei);
    k_alloc<<<(N_NODES + 255) / 256, 256>>>();
    k_scatter<<<(N_EDGES + 255) / 256, 256>>>(ei);
    k_aggregate<<<(N_NODES + NPB - 1) / NPB, 256>>>(x, ea, msg_w, msg_b, self_w, self_b, out);
}